// round 16
// baseline (speedup 1.0000x reference)
#include <cuda_runtime.h>
#include <math.h>

// ---------------------------------------------------------------------------
// HumanPoseModule, joint-parallel with SHUFFLE-fused parent-matrix multiply.
// local_c = R_parent^T @ R_own over RAW 6d->matrix conversions (root cancels).
// One lane per (sample, joint-slot): 16 slots/sample, 2 samples/warp.
// Each lane converts its UNIQUE record; the parent matrix is consumed
// element-by-element directly out of the shuffle (no P[9] live range).
// Root children get identity via per-element FSEL (exact pass-through).
// Outputs assembled in a tiny per-warp smem buffer, stored coalesced.
// ---------------------------------------------------------------------------

#define FDIV(a,b) __fdividef((a),(b))

constexpr int TPB = 256;            // 8 warps, 16 samples per block
constexpr int SPB = 16;

// slot -> own_off(7) | is_ori<<7 | parent_slot<<8 | is_root<<13 | out_off<<16
__constant__ int kSlot[16] = {
    (  0 | 128) | ( 0 << 8) | (1 << 13) | ( 0 << 16),   // j0  = O0 (root)
    (  0      ) | ( 0 << 8) | (1 << 13) | ( 3 << 16),   // j1  = R1
    (  6      ) | ( 0 << 8) | (1 << 13) | ( 6 << 16),   // j2  = R2
    ( 12      ) | ( 0 << 8) | (1 << 13) | ( 9 << 16),   // j3  = R3
    (  6 | 128) | ( 1 << 8) | (0 << 13) | (12 << 16),   // j4  = R1^T O1
    ( 12 | 128) | ( 2 << 8) | (0 << 13) | (15 << 16),   // j5  = R2^T O2
    ( 18      ) | ( 3 << 8) | (0 << 13) | (18 << 16),   // j6  = R3^T R6
    ( 24      ) | ( 6 << 8) | (0 << 13) | (27 << 16),   // j9  = R6^T R9
    ( 30      ) | ( 7 << 8) | (0 << 13) | (36 << 16),   // j12 = R9^T R12
    ( 36      ) | ( 7 << 8) | (0 << 13) | (39 << 16),   // j13 = R9^T R13
    ( 42      ) | ( 7 << 8) | (0 << 13) | (42 << 16),   // j14 = R9^T R14
    ( 18 | 128) | ( 8 << 8) | (0 << 13) | (45 << 16),   // j15 = R12^T O3
    ( 48      ) | ( 9 << 8) | (0 << 13) | (48 << 16),   // j16 = R13^T R16
    ( 54      ) | (10 << 8) | (0 << 13) | (51 << 16),   // j17 = R14^T R17
    ( 24 | 128) | (12 << 8) | (0 << 13) | (54 << 16),   // j18 = R16^T O4
    ( 30 | 128) | (13 << 8) | (0 << 13) | (57 << 16),   // j19 = R17^T O5
};

// Octant-reduced atan2 for y >= 0 (result in [0, pi]); deg-11 minimax, ~2e-8.
__device__ __forceinline__ float fast_atan2_pos(float y, float x) {
    float ax = fabsf(x);
    float mn = fminf(y, ax);
    float mx = fmaxf(y, ax);
    float t  = FDIV(mn, mx);
    float t2 = t * t;
    float p = -0.0117212f;
    p = fmaf(p, t2,  0.05265332f);
    p = fmaf(p, t2, -0.11643287f);
    p = fmaf(p, t2,  0.19354346f);
    p = fmaf(p, t2, -0.33262347f);
    p = fmaf(p, t2,  0.99997726f);
    p = p * t;
    float r = (y > ax) ? (1.57079632679f - p) : p;
    if (x < 0.0f) r = 3.14159265359f - r;
    return r;
}

// matrix -> axis-angle (reference-equivalent; see prior-round derivations)
__device__ __forceinline__ void mat_to_aa(const float m[9],
                                          float& o0, float& o1, float& o2) {
    float m00=m[0], m01=m[1], m02=m[2];
    float m10=m[3], m11=m[4], m12=m[5];
    float m20=m[6], m21=m[7], m22=m[8];

    float w0 = fmaxf(1.0f + m00 + m11 + m22, 0.0f);
    float w1 = fmaxf(1.0f + m00 - m11 - m22, 0.0f);
    float w2 = fmaxf(1.0f - m00 + m11 - m22, 0.0f);
    float w3 = fmaxf(1.0f - m00 - m11 + m22, 0.0f);

    int idx = 0; float best = w0;
    if (w1 > best) { best = w1; idx = 1; }
    if (w2 > best) { best = w2; idx = 2; }
    if (w3 > best) { best = w3; idx = 3; }

    float d21 = m21 - m12, d02 = m02 - m20, d10 = m10 - m01;
    float s10 = m10 + m01, s02 = m02 + m20, s21 = m21 + m12;

    float c0, c1, c2, c3;
    if (idx == 0)      { c0 = w0;  c1 = d21; c2 = d02; c3 = d10; }
    else if (idx == 1) { c0 = d21; c1 = w1;  c2 = s10; c3 = s02; }
    else if (idx == 2) { c0 = d02; c1 = s10; c2 = w2;  c3 = s21; }
    else               { c0 = d10; c1 = s02; c2 = s21; c3 = w3;  }

    float id = 0.5f * rsqrtf(best);     // best >= 1 (traces sum to 4)
    float q0 = c0*id, q1 = c1*id, q2 = c2*id, q3 = c3*id;

    float nrm2 = fmaxf(q1*q1 + q2*q2 + q3*q3, 1e-30f);
    float nrm  = nrm2 * rsqrtf(nrm2);
    float half = fast_atan2_pos(nrm, q0);
    float ang  = 2.0f * half;          // >= 0 always

    float scale;
    if (ang < 1e-6f) {
        scale = FDIV(1.0f, 0.5f - ang*ang*(1.0f/48.0f));
    } else {
        float l2  = nrm2 + q0*q0;           // >= 0.25, never 0
        float len = l2 * rsqrtf(l2);
        scale = FDIV(ang * len, nrm);
    }
    o0 = q1*scale; o1 = q2*scale; o2 = q3*scale;
}

__global__ void __launch_bounds__(TPB)
pose_kernel(const float* __restrict__ glb,   // (BT, 10, 6)
            const float* __restrict__ ori,   // (BT, 6, 6)
            float* __restrict__ out,         // (BT, 24, 3)
            int n)
{
    __shared__ float sout[SPB * 72];         // 4,608 B

    int t    = threadIdx.x;
    int lane = t & 31;
    int warp = t >> 5;
    int s_local  = (warp << 1) | (lane >> 4);            // 0..15
    int slot     = lane & 15;
    int s_global = blockIdx.x * SPB + s_local;
    bool active  = (s_global < n);
    int s_clamp  = active ? s_global : (n - 1);          // convergent loads

    // ---- zero this warp's out region (36 float4 per warp) ----
    {
        float4* z = (float4*)(sout + (warp << 1) * 72);
        z[lane] = make_float4(0.f, 0.f, 0.f, 0.f);
        if (lane < 4) z[lane + 32] = make_float4(0.f, 0.f, 0.f, 0.f);
    }

    int e      = kSlot[slot];
    int parSrc = (lane & 16) | ((e >> 8) & 15);
    bool isRoot = (e & (1 << 13)) != 0;
    int oo     = (e >> 16) & 255;

    // ---- convert own 6d record (unique per lane) ----
    float OWN[9];
    {
        int off = e & 127;
        const float* src = (e & 128) ? (ori + (size_t)s_clamp * 36 + off)
                                     : (glb + (size_t)s_clamp * 60 + off);
        float2 v0 = __ldg((const float2*)(src + 0));
        float2 v1 = __ldg((const float2*)(src + 2));
        float2 v2 = __ldg((const float2*)(src + 4));
        float a1x = v0.x, a1y = v0.y, a1z = v1.x;
        float a2x = v1.y, a2y = v2.x, a2z = v2.y;

        float in1 = rsqrtf(a1x*a1x + a1y*a1y + a1z*a1z);
        float b1x = a1x*in1, b1y = a1y*in1, b1z = a1z*in1;
        float dt = b1x*a2x + b1y*a2y + b1z*a2z;
        float b2x = a2x - dt*b1x, b2y = a2y - dt*b1y, b2z = a2z - dt*b1z;
        float in2 = rsqrtf(b2x*b2x + b2y*b2y + b2z*b2z);
        b2x *= in2; b2y *= in2; b2z *= in2;

        OWN[0]=b1x; OWN[1]=b1y; OWN[2]=b1z;
        OWN[3]=b2x; OWN[4]=b2y; OWN[5]=b2z;
        OWN[6] = b1y*b2z - b1z*b2y;
        OWN[7] = b1z*b2x - b1x*b2z;
        OWN[8] = b1x*b2y - b1y*b2x;
    }

    // ---- L = P^T @ OWN with P elements consumed straight from shuffles ----
    // L[3i+j] = sum_k P[3k+i]*OWN[3k+j]; shuffle order k-major so each
    // shuffled element is used immediately (no P[9] live range).
    // Arithmetic order matches the previous k=0 mul, k=1,2 fma chain.
    float L[9];
#pragma unroll
    for (int k = 0; k < 3; k++) {
#pragma unroll
        for (int i = 0; i < 3; i++) {
            float p = __shfl_sync(0xffffffffu, OWN[3*k + i], parSrc);
            p = isRoot ? ((k == i) ? 1.f : 0.f) : p;
            if (k == 0) {
#pragma unroll
                for (int j = 0; j < 3; j++) L[3*i+j] = p * OWN[j];
            } else {
#pragma unroll
                for (int j = 0; j < 3; j++) L[3*i+j] = fmaf(p, OWN[3*k+j], L[3*i+j]);
            }
        }
    }

    float a0, a1, a2;
    mat_to_aa(L, a0, a1, a2);

    __syncwarp();                          // zero-fill visible before scatter
    if (active) {
        float* po = sout + s_local * 72 + oo;
        po[0] = a0; po[1] = a1; po[2] = a2;
    }
    __syncwarp();

    // ---- coalesced store: warp's 2 samples = 36 float4 ----
    {
        int sw = (blockIdx.x * SPB) + (warp << 1);
        int valid = n - sw; if (valid > 2) valid = 2;
        if (valid > 0) {
            int nf4 = valid * 18;
            const float4* sv = (const float4*)(sout + (warp << 1) * 72);
            float4* dv = (float4*)(out + (size_t)sw * 72);
            if (lane < nf4) dv[lane] = sv[lane];
            if (lane + 32 < nf4) dv[lane + 32] = sv[lane + 32];
        }
    }
}

extern "C" void kernel_launch(void* const* d_in, const int* in_sizes, int n_in,
                              void* d_out, int out_size) {
    const float* glb;
    const float* ori;
    if (in_sizes[0] >= in_sizes[1]) {
        glb = (const float*)d_in[0];
        ori = (const float*)d_in[1];
    } else {
        glb = (const float*)d_in[1];
        ori = (const float*)d_in[0];
    }
    int n = out_size / 72;

    const int blocks = (n + SPB - 1) / SPB;
    pose_kernel<<<blocks, TPB>>>(glb, ori, (float*)d_out, n);
}